// round 15
// baseline (speedup 1.0000x reference)
#include <cuda_runtime.h>
#include <cstdint>
#include <cstddef>

#define BB 2
#define NN 512
#define HH 128
#define DD 128
#define TT 8
#define ZZ 256
#define NTOT 136

// -------- device scratch --------
__device__ float g_m1[BB*NN*DD];   // z@Wm1 + (all msg biases) + graph@Wmg  [receiver]
__device__ float g_m2[BB*NN*DD];   // z@Wm2                                 [sender]
__device__ float g_o1[BB*NN*DD];   // z@Wo1 + bo1 + bo2
__device__ float g_t1[BB*NN*TT];   // z@Wt1 + (all tri biases) + graph@Wtg  [receiver]
__device__ float g_t2[BB*NN*TT];   // z@Wt2                                 [sender]
__device__ unsigned g_msgs[BB*NN*DD]; // encoded-float running max

__device__ __forceinline__ float to_tf32(float x){
  unsigned u; asm("cvt.rna.tf32.f32 %0, %1;" : "=r"(u) : "f"(x));
  return __uint_as_float(u);
}
__device__ __forceinline__ unsigned enc_f(float f){
  unsigned u = __float_as_uint(f);
  return (u & 0x80000000u) ? ~u : (u | 0x80000000u);
}
__device__ __forceinline__ float dec_f(unsigned k){
  unsigned u = (k & 0x80000000u) ? (k & 0x7fffffffu) : ~k;
  return __uint_as_float(u);
}
__device__ __forceinline__ void mma8(float c[4], float a0,float a1,float a2,float a3,
                                     float b0, float b1){
  asm volatile("mma.sync.aligned.m16n8k8.row.col.f32.tf32.tf32.f32 "
      "{%0,%1,%2,%3}, {%4,%5,%6,%7}, {%8,%9}, {%0,%1,%2,%3};\n"
      : "+f"(c[0]), "+f"(c[1]), "+f"(c[2]), "+f"(c[3])
      : "r"(__float_as_uint(a0)), "r"(__float_as_uint(a1)),
        "r"(__float_as_uint(a2)), "r"(__float_as_uint(a3)),
        "r"(__float_as_uint(b0)), "r"(__float_as_uint(b1)));
}
__device__ __forceinline__ void cp16(void* smem, const void* gmem){
  unsigned s = (unsigned)__cvta_generic_to_shared(smem);
  asm volatile("cp.async.cg.shared.global [%0], [%1], 16;\n" :: "r"(s), "l"(gmem));
}
#define CP_COMMIT() asm volatile("cp.async.commit_group;\n" ::: "memory")
#define CP_WAIT1()  asm volatile("cp.async.wait_group 1;\n" ::: "memory")
#define CP_WAIT0()  asm volatile("cp.async.wait_group 0;\n" ::: "memory")

// -------- K1: fused per-node precompute + graph terms + msgs init --------
__global__ void __launch_bounds__(256) k_pre1(
  const float* __restrict__ node, const float* __restrict__ hidden,
  const float* __restrict__ Wm1, const float* __restrict__ Wm2, const float* __restrict__ Wo1,
  const float* __restrict__ Wt1, const float* __restrict__ Wt2,
  const float* __restrict__ bo1, const float* __restrict__ bo2,
  const float* __restrict__ graph, const float* __restrict__ Wmg, const float* __restrict__ Wtg,
  const float* __restrict__ bm1, const float* __restrict__ bm2,
  const float* __restrict__ bme, const float* __restrict__ bmg,
  const float* __restrict__ bt1, const float* __restrict__ bt2,
  const float* __restrict__ bte, const float* __restrict__ btg)
{
  __shared__ float z[8][256];
  __shared__ float red[2][3][8][128];
  __shared__ float smg[128];
  __shared__ float stg[8];
  const int nb0 = blockIdx.x * 8;
  const int b   = nb0 >> 9;          // all 8 nodes share one batch index
  const int tid = threadIdx.x;

  // init g_msgs for this CTA's node range (replaces k_init_msgs)
  for (int idx = tid; idx < 1024; idx += 256)
    g_msgs[(size_t)nb0*DD + idx] = 0x007fffffu;   // enc(-inf)

  for (int idx = tid; idx < 8*256; idx += 256){
    int i = idx >> 8, h = idx & 255;
    int bi = nb0 + i;
    z[i][h] = (h < HH) ? node[bi*HH + h] : hidden[bi*HH + (h - HH)];
  }

  // graph terms (replaces k_pre0): split-h partials into red scratch
  const int d = tid & 127, hv = tid >> 7;
  {
    float s = 0.f;
    const int h0 = hv * 64;
    for (int hh = 0; hh < 64; hh++){
      int h = h0 + hh;
      s += graph[b*HH + h] * Wmg[h*DD + d];
    }
    red[hv][0][0][d] = s;
  }
  __syncthreads();
  if (tid < 128)
    smg[tid] = red[0][0][0][tid] + red[1][0][0][tid]
             + bm1[tid] + bm2[tid] + bme[tid] + bmg[tid];
  else if (tid < 136){
    int t = tid - 128;
    float s2 = bt1[t] + bt2[t] + bte[t] + btg[t];
    for (int h = 0; h < HH; h++) s2 += graph[b*HH + h] * Wtg[h*TT + t];
    stg[t] = s2;
  }
  __syncthreads();

  float a1[8], a2[8], a3[8];
  #pragma unroll
  for (int i = 0; i < 8; i++){ a1[i]=0.f; a2[i]=0.f; a3[i]=0.f; }
  const int h0 = hv * 128;
  for (int hh = 0; hh < 128; hh++){
    int h = h0 + hh;
    float w1 = Wm1[h*DD + d], w2 = Wm2[h*DD + d], w3 = Wo1[h*DD + d];
    #pragma unroll
    for (int i = 0; i < 8; i++){
      float zv = z[i][h];
      a1[i] += zv * w1; a2[i] += zv * w2; a3[i] += zv * w3;
    }
  }
  #pragma unroll
  for (int i = 0; i < 8; i++){
    red[hv][0][i][d] = a1[i]; red[hv][1][i][d] = a2[i]; red[hv][2][i][d] = a3[i];
  }
  __syncthreads();
  for (int idx = tid; idx < 1024; idx += 256){
    int i = idx >> 7, dd = idx & 127;
    int bi = nb0 + i;
    float v1 = red[0][0][i][dd] + red[1][0][i][dd];
    float v2 = red[0][1][i][dd] + red[1][1][i][dd];
    float v3 = red[0][2][i][dd] + red[1][2][i][dd];
    g_m1[(size_t)bi*DD + dd] = v1 + smg[dd];
    g_m2[(size_t)bi*DD + dd] = v2;
    g_o1[(size_t)bi*DD + dd] = v3 + bo1[dd] + bo2[dd];
  }
  if (tid < 128){
    int i = tid >> 4, t = (tid >> 1) & 7, m = tid & 1;
    const float* W = m ? Wt2 : Wt1;
    float s = 0.f;
    for (int h = 0; h < ZZ; h++) s += z[i][h] * W[h*TT + t];
    int bi = nb0 + i;
    if (m == 0) g_t1[(size_t)bi*TT + t] = s + stg[t];
    else        g_t2[(size_t)bi*TT + t] = s;
  }
}

// -------- K2: main fused edge GEMM + triplet relu + masked max --------
// 512 threads = 16 warps: 4 row-groups (16 rows) x 4 col-groups (tiles 5/4/4/3+tri)
#define RB 64
#define SC 64
#define NTHR 512
#define WT_STR 68                 // transposed W row stride in float2 (conflict-free)
// smem layout (float offsets)
#define OFF_W2   0                          // 136 n-rows x 68 float2 = 18496 floats
#define OFF_A    (NTOT*WT_STR*2)            // 18496: 2 bufs x 2 senders x 64x132
#define OFF_M2   (OFF_A + 2*2*64*132)       // 52288: 2 bufs x 2 x 136
#define OFF_ADJ  (OFF_M2 + 2*2*136)         // 52832: 2 bufs x 2 x 64
#define OFF_T1   (OFF_ADJ + 2*2*64)         // 53088: 64 x 8
#define SMEM_WORDS (OFF_T1 + 64*8)          // 53600
#define SMEM_BYTES (SMEM_WORDS*4)           // 214400

__device__ __forceinline__ void prefetch_step(float* smf, const float* edge,
  const float* adj, int b, int r0, int sbase, int buf, int tid)
{
  float* Ab = smf + OFF_A + buf*(2*64*132);
  #pragma unroll
  for (int q = 0; q < 8; q++){
    int i = q*NTHR + tid;
    int jj = i >> 11;                // sender within pair (2048 float4 each)
    int s  = sbase + jj;
    int r  = (i >> 5) & 63;
    int c  = i & 31;
    const float* gp = edge + ((size_t)(b*NN + s)*NN + r0 + r)*HH + c*4;
    cp16(Ab + jj*(64*132) + r*132 + c*4, gp);
  }
  if (tid < 64){
    int jj = tid >> 5, c = tid & 31;
    int s = sbase + jj;
    cp16(smf + OFF_M2 + buf*272 + jj*136 + c*4, g_m2 + (size_t)(b*NN + s)*DD + c*4);
  } else if (tid < 68){
    int q = tid - 64; int jj = q >> 1, c = q & 1;
    int s = sbase + jj;
    cp16(smf + OFF_M2 + buf*272 + jj*136 + 128 + c*4, g_t2 + (size_t)(b*NN + s)*TT + c*4);
  } else if (tid < 100){
    int q = tid - 68; int jj = q >> 4, c = q & 15;
    int s = sbase + jj;
    cp16(smf + OFF_ADJ + buf*128 + jj*64 + c*4, adj + (size_t)(b*NN + s)*NN + r0 + c*4);
  }
}

// NI tiles starting at tile TG0; TRI => last tile is the triplet tile (cols 128..135)
template<int NI, int TG0, bool TRI>
__device__ __forceinline__ void step_compute(
  const float* __restrict__ smf, int buf, int wrow, int g, int tg4,
  float rm[][4], bool& anyM0, bool& anyM1,
  int b, int r0, int sstep, float* __restrict__ triOut)
{
  const float* A0 = smf + OFF_A + buf*(2*64*132) + (wrow + g)*132 + tg4;
  const float* A1 = A0 + 64*132;
  const float2* Wp = (const float2*)smf + (size_t)(TG0*8 + g)*WT_STR + tg4;

  float C0[NI][4], C1[NI][4];
  #pragma unroll
  for (int i = 0; i < NI; i++){
    C0[i][0]=0.f; C0[i][1]=0.f; C0[i][2]=0.f; C0[i][3]=0.f;
    C1[i][0]=0.f; C1[i][1]=0.f; C1[i][2]=0.f; C1[i][3]=0.f;
  }

  #pragma unroll 4
  for (int ks = 0; ks < 16; ks++){
    const float* a0 = A0 + ks*8;
    float x0 = to_tf32(a0[0]), x1 = to_tf32(a0[8*132]);
    float x2 = to_tf32(a0[4]), x3 = to_tf32(a0[8*132 + 4]);
    const float* a1 = A1 + ks*8;
    float y0 = to_tf32(a1[0]), y1 = to_tf32(a1[8*132]);
    float y2 = to_tf32(a1[4]), y3 = to_tf32(a1[8*132 + 4]);
    const float2* wp = Wp + ks*4;
    #pragma unroll
    for (int ni = 0; ni < NI; ni++){
      float2 bb = wp[ni*8*WT_STR];
      mma8(C0[ni], x0,x1,x2,x3, bb.x, bb.y);
      mma8(C1[ni], y0,y1,y2,y3, bb.x, bb.y);
    }
  }

  #pragma unroll
  for (int j = 0; j < 2; j++){
    const float* M2 = smf + OFF_M2 + buf*272 + j*136;
    const float* AD = smf + OFF_ADJ + buf*128 + j*64;
    float adjA = AD[wrow + g];
    float adjB = AD[wrow + 8 + g];
    if (adjA == 0.f) anyM0 = true;
    if (adjB == 0.f) anyM1 = true;
    const float (*C)[4] = j ? C1 : C0;
    const int NM = TRI ? (NI - 1) : NI;
    #pragma unroll
    for (int ni = 0; ni < NM; ni++){
      int n = (TG0 + ni)*8 + 2*tg4;
      float2 m2 = *(const float2*)(M2 + n);
      if (adjA != 0.f){
        rm[ni][0] = fmaxf(rm[ni][0], C[ni][0] + m2.x);
        rm[ni][1] = fmaxf(rm[ni][1], C[ni][1] + m2.y);
      }
      if (adjB != 0.f){
        rm[ni][2] = fmaxf(rm[ni][2], C[ni][2] + m2.x);
        rm[ni][3] = fmaxf(rm[ni][3], C[ni][3] + m2.y);
      }
    }
    if (TRI){
      int tc = 2*tg4;
      float2 m2t = *(const float2*)(M2 + 128 + tc);
      const float* T1 = smf + OFF_T1;
      float2 tA = *(const float2*)(T1 + (wrow + g)*TT + tc);
      float2 tB = *(const float2*)(T1 + (wrow + 8 + g)*TT + tc);
      int s = sstep + j;
      size_t base = (size_t)(b*NN + s)*NN + r0;
      float2 oA, oB;
      oA.x = fmaxf(C[NI-1][0] + tA.x + m2t.x, 0.f);
      oA.y = fmaxf(C[NI-1][1] + tA.y + m2t.y, 0.f);
      oB.x = fmaxf(C[NI-1][2] + tB.x + m2t.x, 0.f);
      oB.y = fmaxf(C[NI-1][3] + tB.y + m2t.y, 0.f);
      *(float2*)(triOut + (base + wrow + g)*TT + tc)     = oA;
      *(float2*)(triOut + (base + wrow + 8 + g)*TT + tc) = oB;
    }
  }
}

template<int NI, int TG0, bool TRI>
__device__ __forceinline__ void flush_rm(const float rm[][4], bool anyM0, bool anyM1,
  int b, int r0, int wrow, int g, int tg4)
{
  const int NM = TRI ? (NI - 1) : NI;
  size_t rowA = (size_t)(b*NN + r0 + wrow + g);
  const float* M1a = g_m1 + rowA*DD;
  const float* M1b = M1a + 8*DD;
  unsigned* Ga = g_msgs + rowA*DD;
  unsigned* Gb = Ga + 8*DD;
  #pragma unroll
  for (int ni = 0; ni < NM; ni++){
    int n = (TG0 + ni)*8 + 2*tg4;
    float2 m1A = *(const float2*)(M1a + n);
    float2 m1B = *(const float2*)(M1b + n);
    float v0 = rm[ni][0] + m1A.x, v1 = rm[ni][1] + m1A.y;
    float v2 = rm[ni][2] + m1B.x, v3 = rm[ni][3] + m1B.y;
    if (anyM0){ v0 = fmaxf(v0, 0.f); v1 = fmaxf(v1, 0.f); }
    if (anyM1){ v2 = fmaxf(v2, 0.f); v3 = fmaxf(v3, 0.f); }
    atomicMax(Ga + n,     enc_f(v0));
    atomicMax(Ga + n + 1, enc_f(v1));
    atomicMax(Gb + n,     enc_f(v2));
    atomicMax(Gb + n + 1, enc_f(v3));
  }
}

__global__ void __launch_bounds__(NTHR, 1) k_main(
  const float* __restrict__ edge, const float* __restrict__ adj,
  const float* __restrict__ Wme, const float* __restrict__ Wte,
  float* __restrict__ triOut)
{
  extern __shared__ float smf[];
  const int tid = threadIdx.x;
  const int b   = blockIdx.z;
  const int r0  = blockIdx.x * RB;
  const int s0  = blockIdx.y * SC;

  // kick off first A-tile prefetch before staging weights
  prefetch_step(smf, edge, adj, b, r0, s0, 0, tid);
  CP_COMMIT();

  // stage W transposed: [n][kk] float2 (kk packs k=8ks+tg4 and +4), stride 68 float2
  for (int idx = tid; idx < NTOT*64; idx += NTHR){
    int n = idx >> 6, kk = idx & 63;
    int klo = (kk >> 2)*8 + (kk & 3), khi = klo + 4;
    float lo = (n < DD) ? Wme[klo*DD + n] : Wte[klo*TT + (n - DD)];
    float hi = (n < DD) ? Wme[khi*DD + n] : Wte[khi*TT + (n - DD)];
    ((float2*)(smf + OFF_W2))[n*WT_STR + kk] = make_float2(to_tf32(lo), to_tf32(hi));
  }
  // stage receiver-side t1
  if (tid < RB*TT)
    smf[OFF_T1 + tid] = g_t1[(size_t)(b*NN + r0)*TT + tid];

  const int w = tid >> 5, lane = tid & 31;
  const int g = lane >> 2, tg4 = lane & 3;
  const int wrow = (w & 3) << 4;     // row group: 4 groups of 16 rows
  const int cg   = w >> 2;           // col group: 0..3

  float rm[5][4];
  const float NEG = __int_as_float(0xff800000);
  #pragma unroll
  for (int i = 0; i < 5; i++){ rm[i][0]=NEG; rm[i][1]=NEG; rm[i][2]=NEG; rm[i][3]=NEG; }
  bool anyM0 = false, anyM1 = false;

  for (int step = 0; step < SC/2; step++){
    int buf = step & 1;
    if (step < SC/2 - 1){
      prefetch_step(smf, edge, adj, b, r0, s0 + (step + 1)*2, buf ^ 1, tid);
      CP_COMMIT();
      CP_WAIT1();
    } else {
      CP_WAIT0();
    }
    __syncthreads();
    if (cg == 0)
      step_compute<5, 0,  false>(smf, buf, wrow, g, tg4, rm, anyM0, anyM1,
                                 b, r0, s0 + step*2, triOut);
    else if (cg == 1)
      step_compute<4, 5,  false>(smf, buf, wrow, g, tg4, rm, anyM0, anyM1,
                                 b, r0, s0 + step*2, triOut);
    else if (cg == 2)
      step_compute<4, 9,  false>(smf, buf, wrow, g, tg4, rm, anyM0, anyM1,
                                 b, r0, s0 + step*2, triOut);
    else
      step_compute<4, 13, true >(smf, buf, wrow, g, tg4, rm, anyM0, anyM1,
                                 b, r0, s0 + step*2, triOut);
    __syncthreads();
  }

  if (cg == 0)      flush_rm<5, 0,  false>(rm, anyM0, anyM1, b, r0, wrow, g, tg4);
  else if (cg == 1) flush_rm<4, 5,  false>(rm, anyM0, anyM1, b, r0, wrow, g, tg4);
  else if (cg == 2) flush_rm<4, 9,  false>(rm, anyM0, anyM1, b, r0, wrow, g, tg4);
  else              flush_rm<4, 13, true >(rm, anyM0, anyM1, b, r0, wrow, g, tg4);
}

// -------- K3: ret = o1full + msgs @ Wo2, 8 nodes/block (128 CTAs) --------
__global__ void __launch_bounds__(256) k_out(
  const float* __restrict__ Wo2, float* __restrict__ ret)
{
  __shared__ float mz[8][128];
  __shared__ float red2[2][8][128];
  const int nb0 = blockIdx.x * 8;
  const int tid = threadIdx.x;
  for (int idx = tid; idx < 8*128; idx += 256){
    int i = idx >> 7, h = idx & 127;
    mz[i][h] = dec_f(g_msgs[(size_t)(nb0 + i)*DD + h]);
  }
  __syncthreads();
  const int d = tid & 127, hv = tid >> 7;
  float acc[8];
  #pragma unroll
  for (int i = 0; i < 8; i++) acc[i] = 0.f;
  const int h0 = hv * 64;
  for (int hh = 0; hh < 64; hh++){
    int h = h0 + hh;
    float wv = Wo2[h*DD + d];
    #pragma unroll
    for (int i = 0; i < 8; i++) acc[i] += mz[i][h] * wv;
  }
  #pragma unroll
  for (int i = 0; i < 8; i++) red2[hv][i][d] = acc[i];
  __syncthreads();
  for (int idx = tid; idx < 8*128; idx += 256){
    int i = idx >> 7, dd = idx & 127;
    int bi = nb0 + i;
    ret[(size_t)bi*DD + dd] = g_o1[(size_t)bi*DD + dd]
                            + red2[0][i][dd] + red2[1][i][dd];
  }
}

// -------- launcher --------
extern "C" void kernel_launch(void* const* d_in, const int* in_sizes, int n_in,
                              void* d_out, int out_size){
  const float* node   = (const float*)d_in[0];
  const float* edge   = (const float*)d_in[1];
  const float* graph  = (const float*)d_in[2];
  const float* adjm   = (const float*)d_in[3];
  const float* hidden = (const float*)d_in[4];
  const float* Wm1 = (const float*)d_in[5];  const float* bm1 = (const float*)d_in[6];
  const float* Wm2 = (const float*)d_in[7];  const float* bm2 = (const float*)d_in[8];
  const float* Wme = (const float*)d_in[9];  const float* bme = (const float*)d_in[10];
  const float* Wmg = (const float*)d_in[11]; const float* bmg = (const float*)d_in[12];
  const float* Wo1 = (const float*)d_in[13]; const float* bo1 = (const float*)d_in[14];
  const float* Wo2 = (const float*)d_in[15]; const float* bo2 = (const float*)d_in[16];
  const float* Wt1 = (const float*)d_in[17]; const float* bt1 = (const float*)d_in[18];
  const float* Wt2 = (const float*)d_in[19]; const float* bt2 = (const float*)d_in[20];
  const float* Wte = (const float*)d_in[21]; const float* bte = (const float*)d_in[22];
  const float* Wtg = (const float*)d_in[23]; const float* btg = (const float*)d_in[24];

  float* ret = (float*)d_out;                 // [2,512,128]
  float* tri = ret + (size_t)BB*NN*DD;        // [2,512,512,8]

  cudaFuncSetAttribute(k_main, cudaFuncAttributeMaxDynamicSharedMemorySize, SMEM_BYTES);

  k_pre1<<<BB*NN/8, 256>>>(node, hidden, Wm1, Wm2, Wo1, Wt1, Wt2, bo1, bo2,
                           graph, Wmg, Wtg, bm1, bm2, bme, bmg, bt1, bt2, bte, btg);
  k_main<<<dim3(NN/RB, NN/SC, BB), NTHR, SMEM_BYTES>>>(edge, adjm, Wme, Wte, tri);
  k_out<<<BB*NN/8, 256>>>(Wo2, ret);
}

// round 17
// speedup vs baseline: 1.4348x; 1.4348x over previous
#include <cuda_runtime.h>
#include <cstdint>
#include <cstddef>

#define BB 2
#define NN 512
#define HH 128
#define DD 128
#define TT 8
#define ZZ 256
#define NTOT 136

// -------- device scratch --------
__device__ float g_m1[BB*NN*DD];   // z@Wm1 + (all msg biases) + graph@Wmg  [receiver]
__device__ float g_m2[BB*NN*DD];   // z@Wm2                                 [sender]
__device__ float g_o1[BB*NN*DD];   // z@Wo1 + bo1 + bo2
__device__ float g_t1[BB*NN*TT];   // z@Wt1 + (all tri biases) + graph@Wtg  [receiver]
__device__ float g_t2[BB*NN*TT];   // z@Wt2                                 [sender]
__device__ float g_mg[BB*DD];
__device__ float g_tg[BB*TT];
__device__ unsigned g_msgs[BB*NN*DD]; // encoded-float running max

__device__ __forceinline__ float to_tf32(float x){
  unsigned u; asm("cvt.rna.tf32.f32 %0, %1;" : "=r"(u) : "f"(x));
  return __uint_as_float(u);
}
__device__ __forceinline__ unsigned enc_f(float f){
  unsigned u = __float_as_uint(f);
  return (u & 0x80000000u) ? ~u : (u | 0x80000000u);
}
__device__ __forceinline__ float dec_f(unsigned k){
  unsigned u = (k & 0x80000000u) ? (k & 0x7fffffffu) : ~k;
  return __uint_as_float(u);
}
__device__ __forceinline__ void mma8(float c[4], float a0,float a1,float a2,float a3,
                                     float b0, float b1){
  asm volatile("mma.sync.aligned.m16n8k8.row.col.f32.tf32.tf32.f32 "
      "{%0,%1,%2,%3}, {%4,%5,%6,%7}, {%8,%9}, {%0,%1,%2,%3};\n"
      : "+f"(c[0]), "+f"(c[1]), "+f"(c[2]), "+f"(c[3])
      : "r"(__float_as_uint(a0)), "r"(__float_as_uint(a1)),
        "r"(__float_as_uint(a2)), "r"(__float_as_uint(a3)),
        "r"(__float_as_uint(b0)), "r"(__float_as_uint(b1)));
}
__device__ __forceinline__ void cp16(void* smem, const void* gmem){
  unsigned s = (unsigned)__cvta_generic_to_shared(smem);
  asm volatile("cp.async.cg.shared.global [%0], [%1], 16;\n" :: "r"(s), "l"(gmem));
}
#define CP_COMMIT() asm volatile("cp.async.commit_group;\n" ::: "memory")
#define CP_WAIT1()  asm volatile("cp.async.wait_group 1;\n" ::: "memory")
#define CP_WAIT0()  asm volatile("cp.async.wait_group 0;\n" ::: "memory")

// -------- K0: graph terms + bias folding (tiny, separate) --------
__global__ void k_pre0(const float* __restrict__ graph,
  const float* __restrict__ Wmg, const float* __restrict__ bm1, const float* __restrict__ bm2,
  const float* __restrict__ bme, const float* __restrict__ bmg,
  const float* __restrict__ Wtg, const float* __restrict__ bt1, const float* __restrict__ bt2,
  const float* __restrict__ bte, const float* __restrict__ btg)
{
  int t = threadIdx.x;
  int b = t >> 7, d = t & 127;
  float s = bm1[d] + bm2[d] + bme[d] + bmg[d];
  for (int h = 0; h < HH; h++) s += graph[b*HH + h] * Wmg[h*DD + d];
  g_mg[t] = s;
  if (t < BB*TT){
    int bb = t >> 3, tt = t & 7;
    float s2 = bt1[tt] + bt2[tt] + bte[tt] + btg[tt];
    for (int h = 0; h < HH; h++) s2 += graph[bb*HH + h] * Wtg[h*TT + tt];
    g_tg[t] = s2;
  }
}

// -------- K1: per-node precompute, 512 threads, 4-way h-split --------
__global__ void __launch_bounds__(512) k_pre1(
  const float* __restrict__ node, const float* __restrict__ hidden,
  const float* __restrict__ Wm1, const float* __restrict__ Wm2, const float* __restrict__ Wo1,
  const float* __restrict__ Wt1, const float* __restrict__ Wt2,
  const float* __restrict__ bo1, const float* __restrict__ bo2)
{
  __shared__ float z[8][256];            // 8 KB
  __shared__ float red[4][3][8][128];    // 48 KB
  const int nb0 = blockIdx.x * 8;
  const int tid = threadIdx.x;
  for (int idx = tid; idx < 8*256; idx += 512){
    int i = idx >> 8, h = idx & 255;
    int bi = nb0 + i;
    z[i][h] = (h < HH) ? node[bi*HH + h] : hidden[bi*HH + (h - HH)];
  }
  __syncthreads();
  const int d = tid & 127, hv = tid >> 7;   // hv in 0..3
  float a1[8], a2[8], a3[8];
  #pragma unroll
  for (int i = 0; i < 8; i++){ a1[i]=0.f; a2[i]=0.f; a3[i]=0.f; }
  const int h0 = hv * 64;
  #pragma unroll 2
  for (int hh = 0; hh < 64; hh++){
    int h = h0 + hh;
    float w1 = Wm1[h*DD + d], w2 = Wm2[h*DD + d], w3 = Wo1[h*DD + d];
    #pragma unroll
    for (int i = 0; i < 8; i++){
      float zv = z[i][h];
      a1[i] += zv * w1; a2[i] += zv * w2; a3[i] += zv * w3;
    }
  }
  #pragma unroll
  for (int i = 0; i < 8; i++){
    red[hv][0][i][d] = a1[i]; red[hv][1][i][d] = a2[i]; red[hv][2][i][d] = a3[i];
  }
  __syncthreads();
  for (int idx = tid; idx < 1024; idx += 512){
    int i = idx >> 7, dd = idx & 127;
    int bi = nb0 + i, b = bi >> 9;
    float v1 = red[0][0][i][dd] + red[1][0][i][dd] + red[2][0][i][dd] + red[3][0][i][dd];
    float v2 = red[0][1][i][dd] + red[1][1][i][dd] + red[2][1][i][dd] + red[3][1][i][dd];
    float v3 = red[0][2][i][dd] + red[1][2][i][dd] + red[2][2][i][dd] + red[3][2][i][dd];
    g_m1[(size_t)bi*DD + dd] = v1 + g_mg[b*DD + dd];
    g_m2[(size_t)bi*DD + dd] = v2;
    g_o1[(size_t)bi*DD + dd] = v3 + bo1[dd] + bo2[dd];
  }
  if (tid < 256){
    // 8 nodes x 8 t x 2 mats x 2 h-halves = 256 partial sums
    int i = tid >> 5, t = (tid >> 2) & 7, m = (tid >> 1) & 1, hh2 = tid & 1;
    const float* W = m ? Wt2 : Wt1;
    float s = 0.f;
    const int hb = hh2 * 128;
    #pragma unroll 2
    for (int h = 0; h < 128; h++) s += z[i][hb + h] * W[(hb + h)*TT + t];
    // reduce pairs via shared scratch (reuse red)
    red[0][0][0][tid >> 1] = (hh2 == 0) ? s : red[0][0][0][tid >> 1];
    __syncwarp();
    if (hh2 == 1){
      float tot = red[0][0][0][tid >> 1] + s;
      int bi = nb0 + i, b = bi >> 9;
      if (m == 0) g_t1[(size_t)bi*TT + t] = tot + g_tg[b*TT + t];
      else        g_t2[(size_t)bi*TT + t] = tot;
    }
  }
}

__global__ void k_init_msgs(){
  int i = blockIdx.x * 256 + threadIdx.x;
  g_msgs[i] = 0x007fffffu;   // enc(-inf)
}

// -------- K2: main fused edge GEMM + triplet relu + masked max (R14, known-good) --------
// 384 threads = 12 warps: 4 row-groups (16 rows each) x 3 col-groups (tiles 6/6/5)
#define RB 64
#define SC 64
#define NTHR 384
#define WT_STR 68                 // transposed W row stride in float2 (conflict-free)
// smem layout (float offsets)
#define OFF_W2   0                          // 136 n-rows x 68 float2 = 18496 floats
#define OFF_A    (NTOT*WT_STR*2)            // 18496: 2 bufs x 2 senders x 64x132
#define OFF_M2   (OFF_A + 2*2*64*132)       // 52288: 2 bufs x 2 x 136
#define OFF_ADJ  (OFF_M2 + 2*2*136)         // 52832: 2 bufs x 2 x 64
#define OFF_T1   (OFF_ADJ + 2*2*64)         // 53088: 64 x 8
#define SMEM_WORDS (OFF_T1 + 64*8)          // 53600
#define SMEM_BYTES (SMEM_WORDS*4)           // 214400

__device__ __forceinline__ void prefetch_step(float* smf, const float* edge,
  const float* adj, int b, int r0, int sbase, int buf, int tid)
{
  float* Ab = smf + OFF_A + buf*(2*64*132);
  for (int i = tid; i < 4096; i += NTHR){
    int jj = i >> 11;                // sender within pair (2048 float4 each)
    int s  = sbase + jj;
    int r  = (i >> 5) & 63;
    int c  = i & 31;
    const float* gp = edge + ((size_t)(b*NN + s)*NN + r0 + r)*HH + c*4;
    cp16(Ab + jj*(64*132) + r*132 + c*4, gp);
  }
  if (tid < 64){
    int jj = tid >> 5, c = tid & 31;
    int s = sbase + jj;
    cp16(smf + OFF_M2 + buf*272 + jj*136 + c*4, g_m2 + (size_t)(b*NN + s)*DD + c*4);
  } else if (tid < 68){
    int q = tid - 64; int jj = q >> 1, c = q & 1;
    int s = sbase + jj;
    cp16(smf + OFF_M2 + buf*272 + jj*136 + 128 + c*4, g_t2 + (size_t)(b*NN + s)*TT + c*4);
  } else if (tid < 100){
    int q = tid - 68; int jj = q >> 4, c = q & 15;
    int s = sbase + jj;
    cp16(smf + OFF_ADJ + buf*128 + jj*64 + c*4, adj + (size_t)(b*NN + s)*NN + r0 + c*4);
  }
}

// NI tiles starting at tile TG0; TRI => last tile is the triplet tile (cols 128..135)
template<int NI, int TG0, bool TRI>
__device__ __forceinline__ void step_compute(
  const float* __restrict__ smf, int buf, int wrow, int g, int tg4,
  float rm[][4], bool& anyM0, bool& anyM1,
  int b, int r0, int sstep, float* __restrict__ triOut)
{
  const float* A0 = smf + OFF_A + buf*(2*64*132) + (wrow + g)*132 + tg4;
  const float* A1 = A0 + 64*132;
  const float2* Wp = (const float2*)smf + (size_t)(TG0*8 + g)*WT_STR + tg4;

  float C0[NI][4], C1[NI][4];
  #pragma unroll
  for (int i = 0; i < NI; i++){
    C0[i][0]=0.f; C0[i][1]=0.f; C0[i][2]=0.f; C0[i][3]=0.f;
    C1[i][0]=0.f; C1[i][1]=0.f; C1[i][2]=0.f; C1[i][3]=0.f;
  }

  #pragma unroll 4
  for (int ks = 0; ks < 16; ks++){
    const float* a0 = A0 + ks*8;
    float x0 = to_tf32(a0[0]), x1 = to_tf32(a0[8*132]);
    float x2 = to_tf32(a0[4]), x3 = to_tf32(a0[8*132 + 4]);
    const float* a1 = A1 + ks*8;
    float y0 = to_tf32(a1[0]), y1 = to_tf32(a1[8*132]);
    float y2 = to_tf32(a1[4]), y3 = to_tf32(a1[8*132 + 4]);
    const float2* wp = Wp + ks*4;
    #pragma unroll
    for (int ni = 0; ni < NI; ni++){
      float2 bb = wp[ni*8*WT_STR];
      mma8(C0[ni], x0,x1,x2,x3, bb.x, bb.y);
      mma8(C1[ni], y0,y1,y2,y3, bb.x, bb.y);
    }
  }

  #pragma unroll
  for (int j = 0; j < 2; j++){
    const float* M2 = smf + OFF_M2 + buf*272 + j*136;
    const float* AD = smf + OFF_ADJ + buf*128 + j*64;
    float adjA = AD[wrow + g];
    float adjB = AD[wrow + 8 + g];
    if (adjA == 0.f) anyM0 = true;
    if (adjB == 0.f) anyM1 = true;
    const float (*C)[4] = j ? C1 : C0;
    const int NM = TRI ? (NI - 1) : NI;
    #pragma unroll
    for (int ni = 0; ni < NM; ni++){
      int n = (TG0 + ni)*8 + 2*tg4;
      float2 m2 = *(const float2*)(M2 + n);
      if (adjA != 0.f){
        rm[ni][0] = fmaxf(rm[ni][0], C[ni][0] + m2.x);
        rm[ni][1] = fmaxf(rm[ni][1], C[ni][1] + m2.y);
      }
      if (adjB != 0.f){
        rm[ni][2] = fmaxf(rm[ni][2], C[ni][2] + m2.x);
        rm[ni][3] = fmaxf(rm[ni][3], C[ni][3] + m2.y);
      }
    }
    if (TRI){
      int tc = 2*tg4;
      float2 m2t = *(const float2*)(M2 + 128 + tc);
      const float* T1 = smf + OFF_T1;
      float2 tA = *(const float2*)(T1 + (wrow + g)*TT + tc);
      float2 tB = *(const float2*)(T1 + (wrow + 8 + g)*TT + tc);
      int s = sstep + j;
      size_t base = (size_t)(b*NN + s)*NN + r0;
      float2 oA, oB;
      oA.x = fmaxf(C[NI-1][0] + tA.x + m2t.x, 0.f);
      oA.y = fmaxf(C[NI-1][1] + tA.y + m2t.y, 0.f);
      oB.x = fmaxf(C[NI-1][2] + tB.x + m2t.x, 0.f);
      oB.y = fmaxf(C[NI-1][3] + tB.y + m2t.y, 0.f);
      *(float2*)(triOut + (base + wrow + g)*TT + tc)     = oA;
      *(float2*)(triOut + (base + wrow + 8 + g)*TT + tc) = oB;
    }
  }
}

template<int NI, int TG0, bool TRI>
__device__ __forceinline__ void flush_rm(const float rm[][4], bool anyM0, bool anyM1,
  int b, int r0, int wrow, int g, int tg4)
{
  const int NM = TRI ? (NI - 1) : NI;
  size_t rowA = (size_t)(b*NN + r0 + wrow + g);
  const float* M1a = g_m1 + rowA*DD;
  const float* M1b = M1a + 8*DD;
  unsigned* Ga = g_msgs + rowA*DD;
  unsigned* Gb = Ga + 8*DD;
  #pragma unroll
  for (int ni = 0; ni < NM; ni++){
    int n = (TG0 + ni)*8 + 2*tg4;
    float2 m1A = *(const float2*)(M1a + n);
    float2 m1B = *(const float2*)(M1b + n);
    float v0 = rm[ni][0] + m1A.x, v1 = rm[ni][1] + m1A.y;
    float v2 = rm[ni][2] + m1B.x, v3 = rm[ni][3] + m1B.y;
    if (anyM0){ v0 = fmaxf(v0, 0.f); v1 = fmaxf(v1, 0.f); }
    if (anyM1){ v2 = fmaxf(v2, 0.f); v3 = fmaxf(v3, 0.f); }
    atomicMax(Ga + n,     enc_f(v0));
    atomicMax(Ga + n + 1, enc_f(v1));
    atomicMax(Gb + n,     enc_f(v2));
    atomicMax(Gb + n + 1, enc_f(v3));
  }
}

__global__ void __launch_bounds__(NTHR, 1) k_main(
  const float* __restrict__ edge, const float* __restrict__ adj,
  const float* __restrict__ Wme, const float* __restrict__ Wte,
  float* __restrict__ triOut)
{
  extern __shared__ float smf[];
  const int tid = threadIdx.x;
  const int b   = blockIdx.z;
  const int r0  = blockIdx.x * RB;
  const int s0  = blockIdx.y * SC;

  // kick off first A-tile prefetch before staging weights
  prefetch_step(smf, edge, adj, b, r0, s0, 0, tid);
  CP_COMMIT();

  // stage W transposed: [n][kk] float2 (kk packs k=8ks+tg4 and +4), stride 68 float2
  for (int idx = tid; idx < NTOT*64; idx += NTHR){
    int n = idx >> 6, kk = idx & 63;
    int klo = (kk >> 2)*8 + (kk & 3), khi = klo + 4;
    float lo = (n < DD) ? Wme[klo*DD + n] : Wte[klo*TT + (n - DD)];
    float hi = (n < DD) ? Wme[khi*DD + n] : Wte[khi*TT + (n - DD)];
    ((float2*)(smf + OFF_W2))[n*WT_STR + kk] = make_float2(to_tf32(lo), to_tf32(hi));
  }
  // stage receiver-side t1
  for (int idx = tid; idx < RB*TT; idx += NTHR)
    smf[OFF_T1 + idx] = g_t1[(size_t)(b*NN + r0)*TT + idx];

  const int w = tid >> 5, lane = tid & 31;
  const int g = lane >> 2, tg4 = lane & 3;
  const int wrow = (w & 3) << 4;     // row group: 4 groups of 16 rows
  const int cg   = w >> 2;           // col group: 0,1,2

  float rm[6][4];
  const float NEG = __int_as_float(0xff800000);
  #pragma unroll
  for (int i = 0; i < 6; i++){ rm[i][0]=NEG; rm[i][1]=NEG; rm[i][2]=NEG; rm[i][3]=NEG; }
  bool anyM0 = false, anyM1 = false;

  for (int step = 0; step < SC/2; step++){
    int buf = step & 1;
    if (step < SC/2 - 1){
      prefetch_step(smf, edge, adj, b, r0, s0 + (step + 1)*2, buf ^ 1, tid);
      CP_COMMIT();
      CP_WAIT1();
    } else {
      CP_WAIT0();
    }
    __syncthreads();
    if (cg == 0)
      step_compute<6, 0,  false>(smf, buf, wrow, g, tg4, rm, anyM0, anyM1,
                                 b, r0, s0 + step*2, triOut);
    else if (cg == 1)
      step_compute<6, 6,  false>(smf, buf, wrow, g, tg4, rm, anyM0, anyM1,
                                 b, r0, s0 + step*2, triOut);
    else
      step_compute<5, 12, true >(smf, buf, wrow, g, tg4, rm, anyM0, anyM1,
                                 b, r0, s0 + step*2, triOut);
    __syncthreads();
  }

  if (cg == 0)      flush_rm<6, 0,  false>(rm, anyM0, anyM1, b, r0, wrow, g, tg4);
  else if (cg == 1) flush_rm<6, 6,  false>(rm, anyM0, anyM1, b, r0, wrow, g, tg4);
  else              flush_rm<5, 12, true >(rm, anyM0, anyM1, b, r0, wrow, g, tg4);
}

// -------- K3: ret = o1full + msgs @ Wo2, 16 nodes/block --------
__global__ void __launch_bounds__(256) k_out(
  const float* __restrict__ Wo2, float* __restrict__ ret)
{
  __shared__ float mz[16][128];
  __shared__ float red2[2][16][128];
  const int nb0 = blockIdx.x * 16;
  const int tid = threadIdx.x;
  for (int idx = tid; idx < 16*128; idx += 256){
    int i = idx >> 7, h = idx & 127;
    mz[i][h] = dec_f(g_msgs[(size_t)(nb0 + i)*DD + h]);
  }
  __syncthreads();
  const int d = tid & 127, hv = tid >> 7;
  float acc[16];
  #pragma unroll
  for (int i = 0; i < 16; i++) acc[i] = 0.f;
  const int h0 = hv * 64;
  for (int hh = 0; hh < 64; hh++){
    int h = h0 + hh;
    float wv = Wo2[h*DD + d];
    #pragma unroll
    for (int i = 0; i < 16; i++) acc[i] += mz[i][h] * wv;
  }
  #pragma unroll
  for (int i = 0; i < 16; i++) red2[hv][i][d] = acc[i];
  __syncthreads();
  for (int idx = tid; idx < 16*128; idx += 256){
    int i = idx >> 7, dd = idx & 127;
    int bi = nb0 + i;
    ret[(size_t)bi*DD + dd] = g_o1[(size_t)bi*DD + dd]
                            + red2[0][i][dd] + red2[1][i][dd];
  }
}

// -------- launcher --------
extern "C" void kernel_launch(void* const* d_in, const int* in_sizes, int n_in,
                              void* d_out, int out_size){
  const float* node   = (const float*)d_in[0];
  const float* edge   = (const float*)d_in[1];
  const float* graph  = (const float*)d_in[2];
  const float* adjm   = (const float*)d_in[3];
  const float* hidden = (const float*)d_in[4];
  const float* Wm1 = (const float*)d_in[5];  const float* bm1 = (const float*)d_in[6];
  const float* Wm2 = (const float*)d_in[7];  const float* bm2 = (const float*)d_in[8];
  const float* Wme = (const float*)d_in[9];  const float* bme = (const float*)d_in[10];
  const float* Wmg = (const float*)d_in[11]; const float* bmg = (const float*)d_in[12];
  const float* Wo1 = (const float*)d_in[13]; const float* bo1 = (const float*)d_in[14];
  const float* Wo2 = (const float*)d_in[15]; const float* bo2 = (const float*)d_in[16];
  const float* Wt1 = (const float*)d_in[17]; const float* bt1 = (const float*)d_in[18];
  const float* Wt2 = (const float*)d_in[19]; const float* bt2 = (const float*)d_in[20];
  const float* Wte = (const float*)d_in[21]; const float* bte = (const float*)d_in[22];
  const float* Wtg = (const float*)d_in[23]; const float* btg = (const float*)d_in[24];

  float* ret = (float*)d_out;                 // [2,512,128]
  float* tri = ret + (size_t)BB*NN*DD;        // [2,512,512,8]

  cudaFuncSetAttribute(k_main, cudaFuncAttributeMaxDynamicSharedMemorySize, SMEM_BYTES);

  k_pre0<<<1, 256>>>(graph, Wmg, bm1, bm2, bme, bmg, Wtg, bt1, bt2, bte, btg);
  k_pre1<<<BB*NN/8, 512>>>(node, hidden, Wm1, Wm2, Wo1, Wt1, Wt2, bo1, bo2);
  k_init_msgs<<<(BB*NN*DD)/256, 256>>>();
  k_main<<<dim3(NN/RB, NN/SC, BB), NTHR, SMEM_BYTES>>>(edge, adjm, Wme, Wte, tri);
  k_out<<<BB*NN/16, 256>>>(Wo2, ret);
}